// round 7
// baseline (speedup 1.0000x reference)
#include <cuda_runtime.h>

// Model_NPZD_68401649156380 — R7: unit-stride float4 row loads + register
// compaction. The used forcing window per (b,w) is the CONTIGUOUS row
// gf[b, 168w .. 168w+167]; cols that matter are multiples of 3 (idx = 168w+3s).
// Load whole rows as float4 (perfect coalescing, 1 wavefront/LDG) and extract
// the stride-3 elements into dense smem during the store:
//   q = 3u   -> cols 12u, 12u+3   -> j = 4u, 4u+1   (v.x, v.w)
//   q = 3u+1 -> col  12u+6        -> j = 4u+2       (v.z)
//   q = 3u+2 -> col  12u+9        -> j = 4u+3       (v.y)
// Block: 256 threads, G=4 batches, 208 ODE threads, pad-57 smem (conflict-free),
// smem-transposed coalesced output (R2 structure, new load engine).

#define NB      2048
#define NWK     52
#define NHRS    8760
#define DT      0.125f
#define NT      256
#define G       4
#define NCOMP   (G * NWK)             // 208
#define WPAD    57
#define ROWQ    42                    // float4 per 168-float row
#define NLD     (2 * G * NWK * ROWQ)  // f4 units per block: 17472
#define SMEM_FLOATS (2 * G * NWK * WPAD)          // 23712
#define SMEM_BYTES  (SMEM_FLOATS * (int)sizeof(float))   // 94848

__global__ __launch_bounds__(NT) void npzd_kernel(
    const float* __restrict__ X_in,     // (B, 52, 5, 1)
    const float* __restrict__ gf,       // (B, 8760)
    const float* __restrict__ gm,       // (B, 8760)
    const float* __restrict__ pv,       // (B, 10)
    float* __restrict__ out)            // (B, 52, 4, 8)
{
    extern __shared__ float sbuf[];     // [2][G][52][57]  (a=0: f, a=1: m)
    const int tid = threadIdx.x;
    const int b0  = blockIdx.x * G;

    // ---- Phase 1: coalesced float4 row loads + stride-3 compaction ----
    // e = ((a*G + g)*52 + w)*42 + q ; consecutive threads -> consecutive q.
    #pragma unroll 4
    for (int e = tid; e < NLD; e += NT) {
        int q  = e % ROWQ;
        int r  = e / ROWQ;
        int w  = r % NWK;
        int r2 = r / NWK;
        int g  = r2 % G;
        int a  = r2 / G;

        const float* src = (a ? gm : gf)
                         + (size_t)(b0 + g) * NHRS + w * 168 + 4 * q;
        float4 v = *(const float4*)src;

        float* drow = sbuf + ((a * G + g) * NWK + w) * WPAD;
        int u  = q / 3;
        int rq = q - 3 * u;
        int j0 = 4 * u;
        if (rq == 0) {
            drow[j0]     = v.x;
            drow[j0 + 1] = v.w;
        } else if (rq == 1) {
            drow[j0 + 2] = v.z;
        } else {
            drow[j0 + 3] = v.y;
        }
    }
    __syncthreads();

    // ---- Phase 2: 56-step Euler recurrence from smem ----
    float o[4][8];
    if (tid < NCOMP) {
        const int g = tid / NWK;
        const int w = tid - g * NWK;
        const int b = b0 + g;

        const float* p = pv + b * 10;
        const float chiC   = p[0];
        const float rho2   = p[1] * 2.0f;
        const float gam01  = p[2] * 0.1f;
        const float lam005 = p[3] * 0.05f;
        const float eps01  = p[4] * 0.1f;
        const float alp03  = p[5] * 0.3f;
        const float bet06  = p[6] * 0.6f;
        const float eta015 = p[7] * 0.15f;
        const float phi04  = p[8] * 0.4f;
        const float zet01  = p[9] * 0.1f;
        const float rem    = 1.0f - alp03 - bet06;

        const float* xi = X_in + ((size_t)(b * NWK + w)) * 5;
        float N = xi[1], P = xi[2], Z = xi[3], D = xi[4];

        const float* sf = sbuf + ((0 * G + g) * NWK + w) * WPAD;
        const float* sm = sbuf + ((1 * G + g) * NWK + w) * WPAD;

        o[0][0] = N; o[1][0] = P; o[2][0] = Z; o[3][0] = D;
        int s = 0;
        #pragma unroll 1
        for (int k = 1; k <= 7; ++k) {
            #pragma unroll
            for (int i = 0; i < 8; ++i, ++s) {
                float ft = sf[s];
                float mt = sm[s];

                float Pc = fmaxf(0.01f, P);
                float Zc = fmaxf(0.01f, Z);
                float gN = N / (chiC + N);
                float zg = rho2 * (1.0f - __expf(-lam005 * Pc)) * Zc;
                float up = gN * ft * Pc;                    // Vm = 1

                float Nn = N + DT * (-up + alp03 * zg + eps01 * P + gam01 * Z
                                     + phi04 * D + mt * (8.0f - N));   // Q0=8
                float Pn = P + DT * (up - zg - eps01 * P - eta015 * P - mt * P);
                float Zn = Z + DT * (bet06 * zg - gam01 * Z - mt * Z);
                float Dn = D + DT * (eta015 * P + rem * zg - phi04 * D
                                     - zet01 * D - mt * D);
                N = Nn; P = Pn; Z = Zn; D = Dn;
            }
            o[0][k] = N; o[1][k] = P; o[2][k] = Z; o[3][k] = D;
        }
    }
    __syncthreads();   // all smem reads done; safe to reuse

    // ---- Phase 3: transpose through smem, coalesced output stores ----
    float* obuf = sbuf;                  // 208*33 = 6864 floats, fits
    if (tid < NCOMP) {
        float* ob = obuf + tid * 33;
        #pragma unroll
        for (int c = 0; c < 4; ++c)
            #pragma unroll
            for (int k = 0; k < 8; ++k)
                ob[c * 8 + k] = o[c][k];
    }
    __syncthreads();

    float* outb = out + (size_t)blockIdx.x * (NCOMP * 32);
    #pragma unroll
    for (int i = tid; i < NCOMP * 32; i += NT) {
        int t2 = i >> 5;
        int m  = i & 31;
        outb[i] = obuf[t2 * 33 + m];
    }
}

extern "C" void kernel_launch(void* const* d_in, const int* in_sizes, int n_in,
                              void* d_out, int out_size)
{
    (void)in_sizes; (void)n_in; (void)out_size;
    const float* X_in = (const float*)d_in[0];
    const float* gf   = (const float*)d_in[1];
    const float* gm   = (const float*)d_in[2];
    const float* pvv  = (const float*)d_in[3];
    float* out        = (float*)d_out;

    cudaFuncSetAttribute(npzd_kernel,
                         cudaFuncAttributeMaxDynamicSharedMemorySize,
                         SMEM_BYTES);
    npzd_kernel<<<NB / G, NT, SMEM_BYTES>>>(X_in, gf, gm, pvv, out);
}

// round 8
// speedup vs baseline: 1.7688x; 1.7688x over previous
#include <cuda_runtime.h>
#include <cstdint>

// Model_NPZD_68401649156380 — R8: TMA 1D bulk-copy load engine.
// Block = 1 batch, 64 threads. The used forcing window per (b,w) is the
// CONTIGUOUS 672B row gf[b, 168w .. 168w+167] (16B aligned & multiple).
// Thread 0 issues 104 cp.async.bulk copies (52 rows x {f,m}) into padded
// 688B smem slots with one mbarrier expect_tx — zero per-thread LDGs.
// Compute: 52 threads run the 56-step recurrence reading raw smem at
// [w*172 + 3s] (<=4-way bank conflict). Epilogue: smem transpose + coalesced
// stores. 71.5KB smem -> 3 blocks/SM; 2048 blocks stagger TMA demand.

#define NB      2048
#define NWK     52
#define NHRS    8760
#define DT      0.125f
#define NT      64
#define ROWF    172                       // padded row stride (floats) = 688B
#define ARRF    (NWK * ROWF)              // 8944 floats per array
#define SMEM_BYTES (2 * ARRF * (int)sizeof(float))   // 71552
#define TX_BYTES   (2 * NWK * 672)        // 69888

__global__ __launch_bounds__(NT, 3) void npzd_kernel(
    const float* __restrict__ X_in,     // (B, 52, 5, 1)
    const float* __restrict__ gf,       // (B, 8760)
    const float* __restrict__ gm,       // (B, 8760)
    const float* __restrict__ pv,       // (B, 10)
    float* __restrict__ out)            // (B, 52, 4, 8)
{
    extern __shared__ float raw[];      // [2][52][172]
    __shared__ __align__(8) unsigned long long mbar;

    const int tid = threadIdx.x;
    const int b   = blockIdx.x;

    uint32_t mb;
    {
        uint64_t a = __cvta_generic_to_shared(&mbar);
        mb = (uint32_t)a;
    }
    uint32_t rawsh = (uint32_t)__cvta_generic_to_shared(raw);

    if (tid == 0) {
        asm volatile("mbarrier.init.shared.b64 [%0], 1;" :: "r"(mb) : "memory");
    }
    __syncthreads();

    if (tid == 0) {
        asm volatile("mbarrier.arrive.expect_tx.shared.b64 _, [%0], %1;"
                     :: "r"(mb), "r"((uint32_t)TX_BYTES) : "memory");
        const float* fb = gf + (size_t)b * NHRS;
        const float* mbp = gm + (size_t)b * NHRS;
        #pragma unroll 4
        for (int w = 0; w < NWK; ++w) {
            const float* srcf = fb + w * 168;
            const float* srcm = mbp + w * 168;
            uint32_t df = rawsh + (uint32_t)(w * ROWF * 4);
            uint32_t dm = rawsh + (uint32_t)((ARRF + w * ROWF) * 4);
            asm volatile(
                "cp.async.bulk.shared::cta.global.mbarrier::complete_tx::bytes"
                " [%0], [%1], %2, [%3];"
                :: "r"(df), "l"(srcf), "r"(672u), "r"(mb) : "memory");
            asm volatile(
                "cp.async.bulk.shared::cta.global.mbarrier::complete_tx::bytes"
                " [%0], [%1], %2, [%3];"
                :: "r"(dm), "l"(srcm), "r"(672u), "r"(mb) : "memory");
        }
    }

    // Overlap parameter/state loads with the TMA flight.
    float chiC=0, rho2=0, gam01=0, lam005=0, eps01=0,
          alp03=0, bet06=0, eta015=0, phi04=0, zet01=0, rem=0;
    float N=0, P=0, Z=0, D=0;
    if (tid < NWK) {
        const float* p = pv + b * 10;
        chiC   = p[0];
        rho2   = p[1] * 2.0f;
        gam01  = p[2] * 0.1f;
        lam005 = p[3] * 0.05f;
        eps01  = p[4] * 0.1f;
        alp03  = p[5] * 0.3f;
        bet06  = p[6] * 0.6f;
        eta015 = p[7] * 0.15f;
        phi04  = p[8] * 0.4f;
        zet01  = p[9] * 0.1f;
        rem    = 1.0f - alp03 - bet06;

        const float* xi = X_in + ((size_t)(b * NWK + tid)) * 5;
        N = xi[1]; P = xi[2]; Z = xi[3]; D = xi[4];
    }

    // Wait for all 104 bulk copies (acquire orders subsequent LDS).
    {
        uint32_t done;
        asm volatile(
            "{\n\t.reg .pred p;\n\t"
            "mbarrier.try_wait.parity.acquire.cta.shared::cta.b64 p, [%1], 0;\n\t"
            "selp.b32 %0, 1, 0, p;\n\t}"
            : "=r"(done) : "r"(mb) : "memory");
        if (!done) {
            asm volatile(
                "{\n\t.reg .pred P1;\n\t"
                "W_%=:\n\t"
                "mbarrier.try_wait.parity.acquire.cta.shared::cta.b64 P1, [%0], 0, 0x989680;\n\t"
                "@P1 bra.uni D_%=;\n\t"
                "bra.uni W_%=;\n\t"
                "D_%=:\n\t}"
                :: "r"(mb) : "memory");
        }
    }

    // ---- 56-step Euler recurrence from raw (strided-3) smem ----
    float o[4][8];
    if (tid < NWK) {
        const float* sf = raw + tid * ROWF;
        const float* sm = raw + ARRF + tid * ROWF;

        o[0][0] = N; o[1][0] = P; o[2][0] = Z; o[3][0] = D;
        int s = 0;
        #pragma unroll 1
        for (int k = 1; k <= 7; ++k) {
            #pragma unroll
            for (int i = 0; i < 8; ++i, ++s) {
                float ft = sf[3 * s];
                float mt = sm[3 * s];

                float Pc = fmaxf(0.01f, P);
                float Zc = fmaxf(0.01f, Z);
                float gN = N / (chiC + N);
                float zg = rho2 * (1.0f - __expf(-lam005 * Pc)) * Zc;
                float up = gN * ft * Pc;                    // Vm = 1

                float Nn = N + DT * (-up + alp03 * zg + eps01 * P + gam01 * Z
                                     + phi04 * D + mt * (8.0f - N));   // Q0=8
                float Pn = P + DT * (up - zg - eps01 * P - eta015 * P - mt * P);
                float Zn = Z + DT * (bet06 * zg - gam01 * Z - mt * Z);
                float Dn = D + DT * (eta015 * P + rem * zg - phi04 * D
                                     - zet01 * D - mt * D);
                N = Nn; P = Pn; Z = Zn; D = Dn;
            }
            o[0][k] = N; o[1][k] = P; o[2][k] = Z; o[3][k] = D;
        }
    }
    __syncthreads();   // smem reads done; reuse raw as transpose buffer

    float* obuf = raw;                   // 52*33 = 1716 floats
    if (tid < NWK) {
        float* ob = obuf + tid * 33;
        #pragma unroll
        for (int c = 0; c < 4; ++c)
            #pragma unroll
            for (int k = 0; k < 8; ++k)
                ob[c * 8 + k] = o[c][k];
    }
    __syncthreads();

    // batch output region: 52*32 = 1664 contiguous floats
    float* outb = out + (size_t)b * (NWK * 32);
    #pragma unroll
    for (int i = tid; i < NWK * 32; i += NT) {
        int t2 = i >> 5;
        int m  = i & 31;
        outb[i] = obuf[t2 * 33 + m];
    }
}

extern "C" void kernel_launch(void* const* d_in, const int* in_sizes, int n_in,
                              void* d_out, int out_size)
{
    (void)in_sizes; (void)n_in; (void)out_size;
    const float* X_in = (const float*)d_in[0];
    const float* gf   = (const float*)d_in[1];
    const float* gm   = (const float*)d_in[2];
    const float* pvv  = (const float*)d_in[3];
    float* out        = (float*)d_out;

    cudaFuncSetAttribute(npzd_kernel,
                         cudaFuncAttributeMaxDynamicSharedMemorySize,
                         SMEM_BYTES);
    npzd_kernel<<<NB, NT, SMEM_BYTES>>>(X_in, gf, gm, pvv, out);
}